// round 1
// baseline (speedup 1.0000x reference)
#include <cuda_runtime.h>
#include <math.h>

// ---------------- problem constants ----------------
#define N_ANG   256
#define DET_V   256
#define DET_U   384
#define VOL_N   128           // VOL_Z == VOL_Y == VOL_X == 128
#define D_SO    500.0f
#define D_SD    1000.0f
#define CU      191.5f        // (DET_U-1)/2
#define CV      127.5f        // (DET_V-1)/2
#define CC      63.5f         // (VOL_N-1)/2
#define ROW_ELEMS (DET_V*DET_U)   // 98304 per angle

// ---------------- device scratch (no allocations allowed) ----------------
__device__ float  g_h[2*DET_U];                       // circular ramp kernel, duplicated
__device__ float2 g_trig[N_ANG];                      // (cos, sin) per angle
__device__ float  g_filt[(size_t)N_ANG*DET_V*DET_U];  // filtered projections (~100 MB)

// ---------------- kernel 0: build h = irfft(ramp) * (pi/N_ANG), and trig table ----------------
__global__ void prep_kernel(const float* __restrict__ ramp) {
    int n = threadIdx.x;
    if (n < DET_U) {
        // h[n] = (1/384)*( X0 + 2*sum_{k=1}^{191} Xk cos(2 pi k n /384) + X192 cos(pi n) )
        double acc = (double)ramp[0];
        for (int k = 1; k < DET_U/2; k++) {
            acc += 2.0 * (double)ramp[k] * cos(2.0 * M_PI * (double)k * (double)n / (double)DET_U);
        }
        acc += (double)ramp[DET_U/2] * cos(M_PI * (double)n);
        float h = (float)(acc / (double)DET_U * (M_PI / (double)N_ANG));
        g_h[n] = h;
        g_h[n + DET_U] = h;
    }
    if (n < N_ANG) {
        double th = (double)n * (2.0 * M_PI / (double)N_ANG);
        g_trig[n] = make_float2((float)cos(th), (float)sin(th));
    }
}

// ---------------- kernel 1: cosine weight + circular convolution (ramp filter) ----------------
// one block per (angle, v) row; 96 threads, 4 outputs/thread, sliding h window
__global__ __launch_bounds__(96) void filt_kernel(const float* __restrict__ proj,
                                                  const float* __restrict__ redund) {
    __shared__ float srow[DET_U];
    __shared__ float sh[2*DET_U];

    int row = blockIdx.x;          // a*DET_V + v
    int a   = row >> 8;
    int v   = row & 255;
    int tid = threadIdx.x;

    float vv  = (float)v - CV;
    float vv2 = D_SD*D_SD + vv*vv;

    const float* prow = proj   + (size_t)row * DET_U;
    const float* rrow = redund + (size_t)a   * DET_U;

    #pragma unroll
    for (int u = tid; u < DET_U; u += 96) {
        float uu = (float)u - CU;
        float cw = D_SD * rsqrtf(vv2 + uu*uu);
        srow[u] = prow[u] * cw * rrow[u];
    }
    for (int i = tid; i < 2*DET_U; i += 96) sh[i] = g_h[i];
    __syncthreads();

    int u0 = tid * 4;
    float a0 = 0.f, a1 = 0.f, a2 = 0.f, a3 = 0.f;
    // window w_j = sh[u0 + j - k + DET_U]
    float w0 = sh[u0 + DET_U + 0];
    float w1 = sh[u0 + DET_U + 1];
    float w2 = sh[u0 + DET_U + 2];
    float w3 = sh[u0 + DET_U + 3];

    #pragma unroll 4
    for (int k = 0; k < DET_U; k++) {
        float rk = srow[k];
        a0 = fmaf(rk, w0, a0);
        a1 = fmaf(rk, w1, a1);
        a2 = fmaf(rk, w2, a2);
        a3 = fmaf(rk, w3, a3);
        // shift window for k+1
        w3 = w2; w2 = w1; w1 = w0;
        w0 = sh[u0 + DET_U - 1 - k];
    }

    float4* dst = reinterpret_cast<float4*>(g_filt + (size_t)row * DET_U + u0);
    *dst = make_float4(a0, a1, a2, a3);
}

// ---------------- kernel 2: backprojection ----------------
#define ZPT 8
__global__ __launch_bounds__(128) void bp_kernel(float* __restrict__ out) {
    __shared__ float2 strig[N_ANG];
    int tid = threadIdx.x;     // x coordinate (warp dim = x for coalescing)
    for (int i = tid; i < N_ANG; i += 128) strig[i] = g_trig[i];
    __syncthreads();

    int x  = tid;
    int y  = blockIdx.x;
    int z0 = blockIdx.y * ZPT;

    float xc  = (float)x  - CC;
    float yc  = (float)y  - CC;
    float zc0 = (float)z0 - CC;

    float acc[ZPT];
    #pragma unroll
    for (int j = 0; j < ZPT; j++) acc[j] = 0.f;

    for (int aIdx = 0; aIdx < N_ANG; aIdx++) {
        float2 cs = strig[aIdx];
        float c = cs.x, s = cs.y;
        float t = yc * c - xc * s;
        float r = D_SO - (xc * c + yc * s);
        float rinv = __fdividef(1.0f, r);

        float iu  = fmaf(D_SD * t, rinv, CU);
        float u0f = floorf(iu);
        float fu  = iu - u0f;
        bool uval = (u0f >= 0.0f) && (u0f <= (float)(DET_U - 2));
        int  u0i  = (int)fminf(fmaxf(u0f, 0.0f), (float)(DET_U - 2));

        float wq = D_SO * rinv;
        float w  = uval ? wq * wq : 0.0f;

        float kz = D_SD * rinv;               // d(iv)/dz
        float iv = fmaf(kz, zc0, CV);

        const float* base = g_filt + (size_t)aIdx * ROW_ELEMS + u0i;

        #pragma unroll
        for (int j = 0; j < ZPT; j++) {
            float v0f = floorf(iv);
            float fv  = iv - v0f;
            float wz  = ((v0f >= 0.0f) && (v0f <= (float)(DET_V - 2))) ? w : 0.0f;
            int   v0i = (int)fminf(fmaxf(v0f, 0.0f), (float)(DET_V - 2));
            const float* p = base + v0i * DET_U;
            float p00 = p[0];
            float p01 = p[1];
            float p10 = p[DET_U];
            float p11 = p[DET_U + 1];
            float aa  = fmaf(fu, p01 - p00, p00);
            float bb  = fmaf(fu, p11 - p10, p10);
            float val = fmaf(fv, bb - aa, aa);
            acc[j] = fmaf(val, wz, acc[j]);
            iv += kz;
        }
    }

    size_t obase = ((size_t)z0 * VOL_N + y) * VOL_N + x;
    #pragma unroll
    for (int j = 0; j < ZPT; j++) {
        out[obase + (size_t)j * VOL_N * VOL_N] = acc[j];
    }
}

// ---------------- launch ----------------
extern "C" void kernel_launch(void* const* d_in, const int* in_sizes, int n_in,
                              void* d_out, int out_size) {
    // robust input mapping by element count
    const float* proj   = nullptr;  // 25165824
    const float* ramp   = nullptr;  // 193
    const float* redund = nullptr;  // 98304
    for (int i = 0; i < n_in; i++) {
        if (in_sizes[i] == DET_U/2 + 1)                    ramp   = (const float*)d_in[i];
        else if (in_sizes[i] == N_ANG * DET_U)             redund = (const float*)d_in[i];
        else if (in_sizes[i] == N_ANG * DET_V * DET_U)     proj   = (const float*)d_in[i];
    }

    prep_kernel<<<1, 384>>>(ramp);
    filt_kernel<<<N_ANG * DET_V, 96>>>(proj, redund);
    dim3 grid(VOL_N, VOL_N / ZPT);
    bp_kernel<<<grid, 128>>>((float*)d_out);
}

// round 2
// speedup vs baseline: 1.3660x; 1.3660x over previous
#include <cuda_runtime.h>
#include <math.h>

// ---------------- problem constants ----------------
#define N_ANG   256
#define DET_V   256
#define DET_U   384
#define VOL_N   128           // VOL_Z == VOL_Y == VOL_X == 128
#define D_SO    500.0f
#define D_SD    1000.0f
#define CU      191.5f        // (DET_U-1)/2
#define CV      127.5f        // (DET_V-1)/2
#define CC      63.5f         // (VOL_N-1)/2
#define ROW_ELEMS (DET_V*DET_U)   // 98304 per angle

// ---------------- device scratch (no allocations allowed) ----------------
__device__ float  g_h[2*DET_U];                       // circular ramp kernel, duplicated
__device__ float2 g_trig[N_ANG];                      // (cos, sin) per angle
__device__ float  g_filt[(size_t)N_ANG*DET_V*DET_U];  // filtered projections (~100 MB)

// ---------------- kernel 0a: trig table ----------------
__global__ void prep_trig_kernel() {
    int a = threadIdx.x;
    float th = (float)a * (2.0f * (float)M_PI / (float)N_ANG);
    float s, c;
    sincosf(th, &s, &c);
    g_trig[a] = make_float2(c, s);
}

// ---------------- kernel 0b: h[n] = irfft(ramp)[n] * (pi/N_ANG), parallel DFT ----------------
// one block per output n; 192 threads, one DFT term each; exact integer phase reduction
__global__ __launch_bounds__(192) void prep_h_kernel(const float* __restrict__ ramp) {
    __shared__ float swarp[6];
    int n = blockIdx.x;
    int k = threadIdx.x;      // 0..191

    float term;
    if (k == 0) {
        // DC + Nyquist terms
        float nyq = ramp[DET_U/2] * (((n & 1) == 0) ? 1.0f : -1.0f);
        term = ramp[0] + nyq;
    } else {
        int m = (k * n) % DET_U;                     // exact phase index
        float ang = (float)m * (2.0f * (float)M_PI / (float)DET_U);
        term = 2.0f * ramp[k] * cosf(ang);
    }

    // warp reduce
    #pragma unroll
    for (int off = 16; off > 0; off >>= 1)
        term += __shfl_down_sync(0xffffffffu, term, off);
    if ((k & 31) == 0) swarp[k >> 5] = term;
    __syncthreads();
    if (k == 0) {
        float acc = 0.f;
        #pragma unroll
        for (int w = 0; w < 6; w++) acc += swarp[w];
        float h = acc * (1.0f / (float)DET_U) * ((float)M_PI / (float)N_ANG);
        g_h[n] = h;
        g_h[n + DET_U] = h;
    }
}

// ---------------- kernel 1: cosine weight + circular convolution (ramp filter) ----------------
// one block per (angle, v) row; 96 threads, 4 outputs/thread, sliding h window
__global__ __launch_bounds__(96) void filt_kernel(const float* __restrict__ proj,
                                                  const float* __restrict__ redund) {
    __shared__ float srow[DET_U];
    __shared__ float sh[2*DET_U];

    int row = blockIdx.x;          // a*DET_V + v
    int a   = row >> 8;
    int v   = row & 255;
    int tid = threadIdx.x;

    float vv  = (float)v - CV;
    float vv2 = D_SD*D_SD + vv*vv;

    const float* prow = proj   + (size_t)row * DET_U;
    const float* rrow = redund + (size_t)a   * DET_U;

    #pragma unroll
    for (int u = tid; u < DET_U; u += 96) {
        float uu = (float)u - CU;
        float cw = D_SD * rsqrtf(vv2 + uu*uu);
        srow[u] = prow[u] * cw * rrow[u];
    }
    for (int i = tid; i < 2*DET_U; i += 96) sh[i] = g_h[i];
    __syncthreads();

    int u0 = tid * 4;
    float a0 = 0.f, a1 = 0.f, a2 = 0.f, a3 = 0.f;
    // window w_j = sh[u0 + j - k + DET_U]
    float w0 = sh[u0 + DET_U + 0];
    float w1 = sh[u0 + DET_U + 1];
    float w2 = sh[u0 + DET_U + 2];
    float w3 = sh[u0 + DET_U + 3];

    #pragma unroll 4
    for (int k = 0; k < DET_U; k++) {
        float rk = srow[k];
        a0 = fmaf(rk, w0, a0);
        a1 = fmaf(rk, w1, a1);
        a2 = fmaf(rk, w2, a2);
        a3 = fmaf(rk, w3, a3);
        // shift window for k+1
        w3 = w2; w2 = w1; w1 = w0;
        w0 = sh[u0 + DET_U - 1 - k];
    }

    float4* dst = reinterpret_cast<float4*>(g_filt + (size_t)row * DET_U + u0);
    *dst = make_float4(a0, a1, a2, a3);
}

// ---------------- kernel 2: backprojection ----------------
#define ZPT 8
__global__ __launch_bounds__(128) void bp_kernel(float* __restrict__ out) {
    __shared__ float2 strig[N_ANG];
    int tid = threadIdx.x;     // x coordinate (warp dim = x for coalescing)
    for (int i = tid; i < N_ANG; i += 128) strig[i] = g_trig[i];
    __syncthreads();

    int x  = tid;
    int y  = blockIdx.x;
    int z0 = blockIdx.y * ZPT;

    float xc  = (float)x  - CC;
    float yc  = (float)y  - CC;
    float zc0 = (float)z0 - CC;

    float acc[ZPT];
    #pragma unroll
    for (int j = 0; j < ZPT; j++) acc[j] = 0.f;

    #pragma unroll 2
    for (int aIdx = 0; aIdx < N_ANG; aIdx++) {
        float2 cs = strig[aIdx];
        float c = cs.x, s = cs.y;
        float t = yc * c - xc * s;
        float r = D_SO - (xc * c + yc * s);
        float rinv = __fdividef(1.0f, r);

        float iu  = fmaf(D_SD * t, rinv, CU);
        float u0f = floorf(iu);
        float fu  = iu - u0f;
        bool uval = (u0f >= 0.0f) && (u0f <= (float)(DET_U - 2));
        int  u0i  = (int)fminf(fmaxf(u0f, 0.0f), (float)(DET_U - 2));

        float wq = D_SO * rinv;
        float w  = uval ? wq * wq : 0.0f;

        float kz = D_SD * rinv;               // d(iv)/dz
        float iv = fmaf(kz, zc0, CV);

        const float* base = g_filt + (size_t)aIdx * ROW_ELEMS + u0i;

        #pragma unroll
        for (int j = 0; j < ZPT; j++) {
            float v0f = floorf(iv);
            float fv  = iv - v0f;
            float wz  = ((v0f >= 0.0f) && (v0f <= (float)(DET_V - 2))) ? w : 0.0f;
            int   v0i = (int)fminf(fmaxf(v0f, 0.0f), (float)(DET_V - 2));
            const float* p = base + v0i * DET_U;
            float p00 = p[0];
            float p01 = p[1];
            float p10 = p[DET_U];
            float p11 = p[DET_U + 1];
            float aa  = fmaf(fu, p01 - p00, p00);
            float bb  = fmaf(fu, p11 - p10, p10);
            float val = fmaf(fv, bb - aa, aa);
            acc[j] = fmaf(val, wz, acc[j]);
            iv += kz;
        }
    }

    size_t obase = ((size_t)z0 * VOL_N + y) * VOL_N + x;
    #pragma unroll
    for (int j = 0; j < ZPT; j++) {
        out[obase + (size_t)j * VOL_N * VOL_N] = acc[j];
    }
}

// ---------------- launch ----------------
extern "C" void kernel_launch(void* const* d_in, const int* in_sizes, int n_in,
                              void* d_out, int out_size) {
    // robust input mapping by element count
    const float* proj   = nullptr;  // 25165824
    const float* ramp   = nullptr;  // 193
    const float* redund = nullptr;  // 98304
    for (int i = 0; i < n_in; i++) {
        if (in_sizes[i] == DET_U/2 + 1)                    ramp   = (const float*)d_in[i];
        else if (in_sizes[i] == N_ANG * DET_U)             redund = (const float*)d_in[i];
        else if (in_sizes[i] == N_ANG * DET_V * DET_U)     proj   = (const float*)d_in[i];
    }

    prep_trig_kernel<<<1, N_ANG>>>();
    prep_h_kernel<<<DET_U, 192>>>(ramp);
    filt_kernel<<<N_ANG * DET_V, 96>>>(proj, redund);
    dim3 grid(VOL_N, VOL_N / ZPT);
    bp_kernel<<<grid, 128>>>((float*)d_out);
}

// round 3
// speedup vs baseline: 2.1643x; 1.5844x over previous
#include <cuda_runtime.h>
#include <cuda_fp16.h>
#include <math.h>

// ---------------- problem constants ----------------
#define N_ANG   256
#define DET_V   256
#define DET_U   384
#define VOL_N   128
#define D_SO    500.0f
#define D_SD    1000.0f
#define CU      191.5f
#define CV      127.5f
#define CC      63.5f
#define ROW_ELEMS (DET_V*DET_U)   // half2 elements per angle slab

// ---------------- device scratch ----------------
__device__ float   g_h[2*DET_U];                         // circular ramp kernel, duplicated
__device__ float2  g_trig[N_ANG];                        // (cos, sin) per angle
__device__ __half2 g_filtH[(size_t)N_ANG*DET_V*DET_U];   // filtered proj, (p[u],p[u+1]) pairs

// ---------------- kernel 0a: trig table (fp64 for accuracy, 1 op/thread) ----------------
__global__ void prep_trig_kernel() {
    int a = threadIdx.x;
    double th = (double)a * (2.0 * M_PI / (double)N_ANG);
    g_trig[a] = make_float2((float)cos(th), (float)sin(th));
}

// ---------------- kernel 0b: h = irfft(ramp) * (pi/N_ANG), fp64 parallel DFT ----------------
__global__ __launch_bounds__(192) void prep_h_kernel(const float* __restrict__ ramp) {
    __shared__ double swarp[6];
    int n = blockIdx.x;
    int k = threadIdx.x;      // 0..191

    double term;
    if (k == 0) {
        double nyq = (double)ramp[DET_U/2] * (((n & 1) == 0) ? 1.0 : -1.0);
        term = (double)ramp[0] + nyq;
    } else {
        int m = (k * n) % DET_U;   // exact phase reduction
        term = 2.0 * (double)ramp[k] * cos(2.0 * M_PI * (double)m / (double)DET_U);
    }
    #pragma unroll
    for (int off = 16; off > 0; off >>= 1)
        term += __shfl_down_sync(0xffffffffu, term, off);
    if ((k & 31) == 0) swarp[k >> 5] = term;
    __syncthreads();
    if (k == 0) {
        double acc = 0.0;
        #pragma unroll
        for (int w = 0; w < 6; w++) acc += swarp[w];
        float h = (float)(acc / (double)DET_U * (M_PI / (double)N_ANG));
        g_h[n] = h;
        g_h[n + DET_U] = h;
    }
}

// ---------------- kernel 1: weight + circular conv, chunked register-blocked ----------------
// one block per (angle, v) row; 96 threads, 4 outputs/thread
// 16 FMAs per 4-tap chunk using ping-ponged float4 h-windows
#define CONV16(rk, p, q)                              \
    a0 = fmaf((rk).x, (q).x, a0);                     \
    a1 = fmaf((rk).x, (q).y, a1);                     \
    a2 = fmaf((rk).x, (q).z, a2);                     \
    a3 = fmaf((rk).x, (q).w, a3);                     \
    a0 = fmaf((rk).y, (p).w, a0);                     \
    a1 = fmaf((rk).y, (q).x, a1);                     \
    a2 = fmaf((rk).y, (q).y, a2);                     \
    a3 = fmaf((rk).y, (q).z, a3);                     \
    a0 = fmaf((rk).z, (p).z, a0);                     \
    a1 = fmaf((rk).z, (p).w, a1);                     \
    a2 = fmaf((rk).z, (q).x, a2);                     \
    a3 = fmaf((rk).z, (q).y, a3);                     \
    a0 = fmaf((rk).w, (p).y, a0);                     \
    a1 = fmaf((rk).w, (p).z, a1);                     \
    a2 = fmaf((rk).w, (p).w, a2);                     \
    a3 = fmaf((rk).w, (q).x, a3);

__global__ __launch_bounds__(96) void filt_kernel(const float* __restrict__ proj,
                                                  const float* __restrict__ redund) {
    __shared__ float srow[DET_U];
    __shared__ float sh[2*DET_U];

    int row = blockIdx.x;          // a*DET_V + v
    int a   = row >> 8;
    int v   = row & 255;
    int tid = threadIdx.x;

    float vv  = (float)v - CV;
    float vv2 = D_SD*D_SD + vv*vv;

    const float* prow = proj   + (size_t)row * DET_U;
    const float* rrow = redund + (size_t)a   * DET_U;

    #pragma unroll
    for (int u = tid; u < DET_U; u += 96) {
        float uu = (float)u - CU;
        float cw = D_SD * rsqrtf(vv2 + uu*uu);
        srow[u] = prow[u] * cw * rrow[u];
    }
    for (int i = tid; i < 2*DET_U; i += 96) sh[i] = g_h[i];
    __syncthreads();

    int u0 = tid * 4;
    float a0 = 0.f, a1 = 0.f, a2 = 0.f, a3 = 0.f;

    // out[u0+j] = sum_k srow[k] * sh[u0 + 384 + j - k]
    float4 cur = *(const float4*)&sh[u0 + DET_U];
    #pragma unroll 6
    for (int c = 0; c < 96; c += 2) {
        float4 rk  = *(const float4*)&srow[4*c];
        float4 prv = *(const float4*)&sh[u0 + DET_U - 4 - 4*c];
        CONV16(rk, prv, cur);
        float4 rk2  = *(const float4*)&srow[4*c + 4];
        float4 prv2 = *(const float4*)&sh[u0 + DET_U - 8 - 4*c];
        CONV16(rk2, prv2, prv);
        cur = prv2;
    }

    // stage outputs in smem (reuse sh), then pack (p[u], p[u+1]) half2 pairs
    __syncthreads();
    sh[u0 + 0] = a0;
    sh[u0 + 1] = a1;
    sh[u0 + 2] = a2;
    sh[u0 + 3] = a3;
    __syncthreads();

    float o0 = sh[u0 + 0];
    float o1 = sh[u0 + 1];
    float o2 = sh[u0 + 2];
    float o3 = sh[u0 + 3];
    float o4 = (u0 == DET_U - 4) ? 0.0f : sh[u0 + 4];

    __half2 h0 = __floats2half2_rn(o0, o1);
    __half2 h1 = __floats2half2_rn(o1, o2);
    __half2 h2 = __floats2half2_rn(o2, o3);
    __half2 h3 = __floats2half2_rn(o3, o4);

    uint4 pack;
    pack.x = *reinterpret_cast<unsigned int*>(&h0);
    pack.y = *reinterpret_cast<unsigned int*>(&h1);
    pack.z = *reinterpret_cast<unsigned int*>(&h2);
    pack.w = *reinterpret_cast<unsigned int*>(&h3);
    uint4* dst = reinterpret_cast<uint4*>(g_filtH + (size_t)row * DET_U + u0);
    *dst = pack;
}

// ---------------- kernel 2: backprojection (half2 u-pair loads) ----------------
#define ZPT 8
__global__ __launch_bounds__(128) void bp_kernel(float* __restrict__ out) {
    __shared__ float2 strig[N_ANG];
    int tid = threadIdx.x;     // x coordinate (warp dim = x)
    for (int i = tid; i < N_ANG; i += 128) strig[i] = g_trig[i];
    __syncthreads();

    int x  = tid;
    int y  = blockIdx.x;
    int z0 = blockIdx.y * ZPT;

    float xc  = (float)x  - CC;
    float yc  = (float)y  - CC;
    float zc0 = (float)z0 - CC;

    float acc[ZPT];
    #pragma unroll
    for (int j = 0; j < ZPT; j++) acc[j] = 0.f;

    #pragma unroll 2
    for (int aIdx = 0; aIdx < N_ANG; aIdx++) {
        float2 cs = strig[aIdx];
        float c = cs.x, s = cs.y;
        float t = yc * c - xc * s;
        float r = D_SO - (xc * c + yc * s);
        float rinv = __fdividef(1.0f, r);

        float iu  = fmaf(D_SD * t, rinv, CU);
        float u0f = floorf(iu);
        float fu  = iu - u0f;
        bool uval = (u0f >= 0.0f) && (u0f <= (float)(DET_U - 2));
        int  u0i  = (int)fminf(fmaxf(u0f, 0.0f), (float)(DET_U - 2));

        float wq = D_SO * rinv;
        float w  = uval ? wq * wq : 0.0f;

        float kz = D_SD * rinv;               // d(iv)/dz
        float iv = fmaf(kz, zc0, CV);

        const __half2* base = g_filtH + (size_t)aIdx * ROW_ELEMS + u0i;

        #pragma unroll
        for (int j = 0; j < ZPT; j++) {
            float v0f = floorf(iv);
            float fv  = iv - v0f;
            float wz  = ((v0f >= 0.0f) && (v0f <= (float)(DET_V - 2))) ? w : 0.0f;
            int   v0i = (int)fminf(fmaxf(v0f, 0.0f), (float)(DET_V - 2));
            const __half2* p = base + v0i * DET_U;
            float2 f0 = __half22float2(p[0]);       // (p00, p01)
            float2 f1 = __half22float2(p[DET_U]);   // (p10, p11)
            float aa  = fmaf(fu, f0.y - f0.x, f0.x);
            float bb  = fmaf(fu, f1.y - f1.x, f1.x);
            float val = fmaf(fv, bb - aa, aa);
            acc[j] = fmaf(val, wz, acc[j]);
            iv += kz;
        }
    }

    size_t obase = ((size_t)z0 * VOL_N + y) * VOL_N + x;
    #pragma unroll
    for (int j = 0; j < ZPT; j++) {
        out[obase + (size_t)j * VOL_N * VOL_N] = acc[j];
    }
}

// ---------------- launch ----------------
extern "C" void kernel_launch(void* const* d_in, const int* in_sizes, int n_in,
                              void* d_out, int out_size) {
    const float* proj   = nullptr;
    const float* ramp   = nullptr;
    const float* redund = nullptr;
    for (int i = 0; i < n_in; i++) {
        if (in_sizes[i] == DET_U/2 + 1)                    ramp   = (const float*)d_in[i];
        else if (in_sizes[i] == N_ANG * DET_U)             redund = (const float*)d_in[i];
        else if (in_sizes[i] == N_ANG * DET_V * DET_U)     proj   = (const float*)d_in[i];
    }

    prep_trig_kernel<<<1, N_ANG>>>();
    prep_h_kernel<<<DET_U, 192>>>(ramp);
    filt_kernel<<<N_ANG * DET_V, 96>>>(proj, redund);
    dim3 grid(VOL_N, VOL_N / ZPT);
    bp_kernel<<<grid, 128>>>((float*)d_out);
}